// round 3
// baseline (speedup 1.0000x reference)
#include <cuda_runtime.h>
#include <cstdint>

// ---------------------------------------------------------------------------
// GPTQ 4-bit dequant GEMM, tf32 tensor cores (mma.sync m16n8k8), fp32 accum.
// C[M,N] = A[M,K] @ dequant(QW)   with group-128 scales/zeros along K.
// Block tile 128x128x32, 8 warps (2x4), warp tile 64x32.
// ---------------------------------------------------------------------------

#define LDSM4(R0,R1,R2,R3,addr) \
  asm volatile("ldmatrix.sync.aligned.m8n8.x4.shared.b16 {%0,%1,%2,%3}, [%4];" \
    : "=r"(R0),"=r"(R1),"=r"(R2),"=r"(R3) : "r"(addr))

#define MMA8(Cr,A0,A1,A2,A3,B0,B1) \
  asm volatile("mma.sync.aligned.m16n8k8.row.col.f32.tf32.tf32.f32 " \
    "{%0,%1,%2,%3},{%4,%5,%6,%7},{%8,%9},{%0,%1,%2,%3};" \
    : "+f"(Cr[0]),"+f"(Cr[1]),"+f"(Cr[2]),"+f"(Cr[3]) \
    : "r"(A0),"r"(A1),"r"(A2),"r"(A3),"r"(B0),"r"(B1))

__device__ __forceinline__ uint32_t f2tf32(float x){
  uint32_t r; asm("cvt.rna.tf32.f32 %0, %1;" : "=r"(r) : "f"(x)); return r;
}

__global__ void __launch_bounds__(256)
gptq_gemm_tf32(const float* __restrict__ A, const int* __restrict__ QW,
               const float* __restrict__ SC, const int* __restrict__ QZ,
               float* __restrict__ C, int M, int N, int K)
{
  // smem: 2 stages x (A: 128x32 tf32 = 4096 words, B: 128x32 tf32 = 4096 words)
  extern __shared__ uint32_t smem[];

  const int tid  = threadIdx.x;
  const int lane = tid & 31, warp = tid >> 5;
  const int wm   = warp >> 2, wn = warp & 3;       // 2 (M) x 4 (N) warp grid
  const int bm   = blockIdx.y, bn = blockIdx.x;

  // ---- ldmatrix per-thread address components (byte offsets in a stage) ----
  const int lm8 = lane & 7;
  const uint32_t sbase = (uint32_t)__cvta_generic_to_shared(smem);
  uint32_t rowA[4], rowB[2], kA[4], kB[4];
#pragma unroll
  for (int mt = 0; mt < 4; mt++)   // A tiles: m16 slices of warp's 64 rows
    rowA[mt] = (uint32_t)((wm*64 + mt*16 + ((lane>>3)&1)*8 + lm8) * 128);
#pragma unroll
  for (int j = 0; j < 2; j++)      // B: two ldsm.x4, each covers 16 n
    rowB[j]  = (uint32_t)((wn*32 + j*16 + ((lane>>4)&1)*8 + lm8) * 128);
#pragma unroll
  for (int ks = 0; ks < 4; ks++){  // k-step within BK=32 (k8 each)
    kA[ks] = (uint32_t)(((2*ks + (lane>>4))      ^ lm8) << 4);
    kB[ks] = (uint32_t)(((2*ks + ((lane>>3)&1))  ^ lm8) << 4);
  }

  // ---- global load coordinates ----
  const int arow = tid >> 3;         // A: 0..31 (x4 passes of 32 rows)
  const int acol = (tid & 7) * 4;    // float4 column
  const int nn   = tid & 127;        // B column within tile
  const int wrb  = tid >> 7;         // first qweight word-row (0/1; +2 for 2nd)
  const int ngl  = bn*128 + nn;      // global n for this thread's B column
  const int N8   = N >> 3;

  const float* Abase = A + (size_t)(bm*128 + arow)*K + acol;

  float4   aReg[4];
  unsigned wReg[2];
  float    zf = 0.f, sf = 0.f;

  float c[4][4][4];
#pragma unroll
  for (int i=0;i<4;i++)
#pragma unroll
    for (int j=0;j<4;j++)
#pragma unroll
      for (int q=0;q<4;q++) c[i][j][q]=0.f;

  const int NK = K >> 5;  // BK = 32

  // ---- tile load into registers ----
  auto LOAD = [&](int kt){
#pragma unroll
    for (int p = 0; p < 4; p++)
      aReg[p] = *reinterpret_cast<const float4*>(Abase + (size_t)p*32*K + kt*32);
    int wrow = kt*4 + wrb;
    wReg[0] = (unsigned)QW[(size_t)wrow*N + ngl];
    wReg[1] = (unsigned)QW[(size_t)(wrow+2)*N + ngl];
    int g  = kt >> 2;                               // GROUP=128 = 4 BK tiles
    int zw = QZ[(size_t)g*N8 + (ngl>>3)];
    zf = (float)(((zw >> ((ngl&7)*4)) & 15) + 1);
    sf = SC[(size_t)g*N + ngl];
  };

  // ---- dequant + tf32 round + swizzled smem store ----
  auto STORE = [&](int stage){
    uint32_t* sA = smem + stage*8192;
    uint32_t* sB = sA + 4096;
#pragma unroll
    for (int p = 0; p < 4; p++){
      int r = arow + p*32;
      uint32_t* dst = sA + r*32 + (((tid&7) ^ (r&7)) << 2);
      uint4 v;
      v.x = f2tf32(aReg[p].x); v.y = f2tf32(aReg[p].y);
      v.z = f2tf32(aReg[p].z); v.w = f2tf32(aReg[p].w);
      *reinterpret_cast<uint4*>(dst) = v;
    }
    uint32_t* rowp = sB + nn*32;
#pragma unroll
    for (int i = 0; i < 2; i++){
      int wr = wrb + 2*i;
      unsigned w = wReg[i];
#pragma unroll
      for (int jj = 0; jj < 2; jj++){
        int sh = jj*16;
        float t0 = ((float)(int)((w >> (sh     )) & 15u) - zf) * sf;
        float t1 = ((float)(int)((w >> (sh +  4)) & 15u) - zf) * sf;
        float t2 = ((float)(int)((w >> (sh +  8)) & 15u) - zf) * sf;
        float t3 = ((float)(int)((w >> (sh + 12)) & 15u) - zf) * sf;
        uint4 v;
        v.x = f2tf32(t0); v.y = f2tf32(t1); v.z = f2tf32(t2); v.w = f2tf32(t3);
        uint32_t* dst = rowp + ((((wr<<1)+jj) ^ (nn&7)) << 2);
        *reinterpret_cast<uint4*>(dst) = v;
      }
    }
  };

  // ---- mma over one BK=32 slab ----
  auto COMPUTE = [&](int stage){
    uint32_t aB = sbase + (uint32_t)stage*32768u;
    uint32_t bB = aB + 16384u;
#pragma unroll
    for (int ks = 0; ks < 4; ks++){
      uint32_t af[4][4], bf[2][4];
#pragma unroll
      for (int mt = 0; mt < 4; mt++)
        LDSM4(af[mt][0],af[mt][1],af[mt][2],af[mt][3], aB + rowA[mt] + kA[ks]);
#pragma unroll
      for (int j = 0; j < 2; j++)
        LDSM4(bf[j][0],bf[j][1],bf[j][2],bf[j][3], bB + rowB[j] + kB[ks]);
#pragma unroll
      for (int mt = 0; mt < 4; mt++)
#pragma unroll
        for (int nt = 0; nt < 4; nt++)
          MMA8(c[mt][nt], af[mt][0],af[mt][1],af[mt][2],af[mt][3],
               bf[nt>>1][(nt&1)*2], bf[nt>>1][(nt&1)*2+1]);
    }
  };

  // ---- pipelined main loop (double-buffered smem) ----
  LOAD(0);
  STORE(0);
  __syncthreads();
  for (int kt = 0; kt < NK; kt++){
    if (kt + 1 < NK) LOAD(kt + 1);
    COMPUTE(kt & 1);
    if (kt + 1 < NK) STORE((kt + 1) & 1);
    __syncthreads();
  }

  // ---- epilogue: fp32 accumulators -> C ----
  const int g  = lane >> 2, t4 = lane & 3;
  const size_t rbase = (size_t)(bm*128 + wm*64);
  const int    cbase = bn*128 + wn*32 + 2*t4;
#pragma unroll
  for (int mt = 0; mt < 4; mt++){
#pragma unroll
    for (int nt = 0; nt < 4; nt++){
      size_t o0 = (rbase + mt*16 + g) * (size_t)N + cbase + nt*8;
      *reinterpret_cast<float2*>(C + o0) =
          make_float2(c[mt][nt][0], c[mt][nt][1]);
      *reinterpret_cast<float2*>(C + o0 + (size_t)8*N) =
          make_float2(c[mt][nt][2], c[mt][nt][3]);
    }
  }
}

extern "C" void kernel_launch(void* const* d_in, const int* in_sizes, int n_in,
                              void* d_out, int out_size)
{
  const float* x  = (const float*)d_in[0];
  const int*   qw = (const int*)  d_in[1];
  const float* sc = (const float*)d_in[2];
  const int*   qz = (const int*)  d_in[3];
  // g_idx (d_in[4]) is standard consecutive grouping; used only for sizes.

  const int K = in_sizes[4];              // g_idx has K entries
  const int M = in_sizes[0] / K;          // x is M*K
  const int G = K / 128;                  // GROUP = 128
  const int N = in_sizes[2] / G;          // scales is G*N

  const size_t shmem = 2 * 8192 * sizeof(uint32_t);  // 64 KB
  cudaFuncSetAttribute(gptq_gemm_tf32,
                       cudaFuncAttributeMaxDynamicSharedMemorySize,
                       (int)shmem);

  dim3 grid(N / 128, M / 128);
  gptq_gemm_tf32<<<grid, 256, shmem>>>(x, qw, sc, qz, (float*)d_out, M, N, K);
}

// round 5
// speedup vs baseline: 1.3485x; 1.3485x over previous
#include <cuda_runtime.h>
#include <cuda_fp16.h>
#include <cstdint>

// ---------------------------------------------------------------------------
// GPTQ 4-bit dequant GEMM, fp16 tensor cores (mma.sync m16n8k16), fp32 accum.
// C[M,N] = A[M,K] @ dequant(QW)   with group-128 scales/zeros along K.
// Block tile 128x128x32, 8 warps (2x4), warp tile 64x32.
// A and dequantized B stored in smem as fp16, 64B rows, XOR-4 16B-chunk swizzle.
// ---------------------------------------------------------------------------

#define LDSM4(R0,R1,R2,R3,addr) \
  asm volatile("ldmatrix.sync.aligned.m8n8.x4.shared.b16 {%0,%1,%2,%3}, [%4];" \
    : "=r"(R0),"=r"(R1),"=r"(R2),"=r"(R3) : "r"(addr))

#define MMA16(Cr,A0,A1,A2,A3,B0,B1) \
  asm volatile("mma.sync.aligned.m16n8k16.row.col.f32.f16.f16.f32 " \
    "{%0,%1,%2,%3},{%4,%5,%6,%7},{%8,%9},{%0,%1,%2,%3};" \
    : "+f"(Cr[0]),"+f"(Cr[1]),"+f"(Cr[2]),"+f"(Cr[3]) \
    : "r"(A0),"r"(A1),"r"(A2),"r"(A3),"r"(B0),"r"(B1))

__device__ __forceinline__ uint32_t f16x2(float lo, float hi){
  uint32_t r; asm("cvt.rn.f16x2.f32 %0, %2, %1;" : "=r"(r) : "f"(lo), "f"(hi)); return r;
}

__global__ void __launch_bounds__(256, 2)
gptq_gemm_f16(const float* __restrict__ A, const int* __restrict__ QW,
              const float* __restrict__ SC, const int* __restrict__ QZ,
              float* __restrict__ C, int M, int N, int K)
{
  // smem: 2 stages x (A: 128 rows x 64B + B: 128 rows x 64B) = 2 x 16KB
  extern __shared__ char smem[];

  const int tid  = threadIdx.x;
  const int lane = tid & 31, warp = tid >> 5;
  const int wm   = warp >> 2, wn = warp & 3;       // 2 (M) x 4 (N) warp grid
  const int bm   = blockIdx.y, bn = blockIdx.x;

  // ---- ldmatrix per-thread address components (byte offsets in a stage) ----
  const uint32_t sbase = (uint32_t)__cvta_generic_to_shared(smem);
  uint32_t rowA[4], rowB[2], kOff[2];
#pragma unroll
  for (int mt = 0; mt < 4; mt++)   // A: m16 slices; lanes 0-15 rows, 16-31 k-hi
    rowA[mt] = (uint32_t)((wm*64 + mt*16 + (lane & 15)) * 64);
#pragma unroll
  for (int j = 0; j < 2; j++)      // B: each ldsm.x4 covers n16 x k16
    rowB[j]  = (uint32_t)((wn*32 + j*16 + ((lane>>3)&1)*8 + (lane&7)) * 64);
#pragma unroll
  for (int ks = 0; ks < 2; ks++)   // 16B chunk: (2ks + khalf) ^ (row&3)
    kOff[ks] = (uint32_t)(((2*ks + (lane>>4)) ^ (lane & 3)) << 4);

  // ---- global load coordinates ----
  const int arow = tid >> 2;         // A: rows 0..63 (+64 on 2nd pass)
  const int aq   = tid & 3;          // 16B chunk (8 fp32 cols) within row
  const int nn   = tid & 127;        // B n-row within tile
  const int half = tid >> 7;         // k-half (16 k) handled by this thread
  const int ngl  = bn*128 + nn;
  const int zsh  = (ngl & 7) * 4;
  const int N8   = N >> 3;

  const float* Abase = A + (size_t)(bm*128 + arow)*K + aq*8;

  float4   aR[2][4];                 // 2 passes x 2 float4 each
  unsigned wR[2];
  uint32_t zc2 = 0; 
  __half2  s2  = __half2half2(__float2half(0.f));

  float c[4][4][4];
#pragma unroll
  for (int i=0;i<4;i++)
#pragma unroll
    for (int j=0;j<4;j++)
#pragma unroll
      for (int q=0;q<4;q++) c[i][j][q]=0.f;

  const int NK = K >> 5;  // BK = 32

  // ---- tile load into registers ----
  auto LOAD = [&](int kt){
#pragma unroll
    for (int p = 0; p < 2; p++){
      aR[p][0] = *reinterpret_cast<const float4*>(Abase + (size_t)p*64*K + kt*32);
      aR[p][1] = *reinterpret_cast<const float4*>(Abase + (size_t)p*64*K + kt*32 + 4);
    }
    const int wrow = kt*4 + half*2;
    wR[0] = (unsigned)QW[(size_t)wrow*N + ngl];
    wR[1] = (unsigned)QW[(size_t)(wrow+1)*N + ngl];
    const int g = kt >> 2;                          // GROUP=128 = 4 BK tiles
    const int zq = (QZ[(size_t)g*N8 + (ngl>>3)] >> zsh) & 15;
    const uint32_t zb = 0x6400u + 1u + (uint32_t)zq; // fp16 bits of 1025+z (exact)
    zc2 = zb | (zb << 16);
    s2  = __half2half2(__float2half(SC[(size_t)g*N + ngl]));
  };

  // ---- convert/dequant + swizzled smem store ----
  auto STORE = [&](int stage){
    char* sA = smem + stage*16384;
    char* sB = sA + 8192;
    // A: fp32 -> fp16, 8 halves (16B) per row-chunk
#pragma unroll
    for (int p = 0; p < 2; p++){
      const int r = arow + p*64;
      uint32_t off = (uint32_t)(r*64) + (uint32_t)(((aq) ^ (r&3)) << 4);
      uint4 v;
      v.x = f16x2(aR[p][0].x, aR[p][0].y);
      v.y = f16x2(aR[p][0].z, aR[p][0].w);
      v.z = f16x2(aR[p][1].x, aR[p][1].y);
      v.w = f16x2(aR[p][1].z, aR[p][1].w);
      *reinterpret_cast<uint4*>(sA + off) = v;
    }
    // B: packed half2 dequant. h = 1024+nib (exact), h - (1025+z) exact,
    // one rounded hmul2 by scale.
#pragma unroll
    for (int wi = 0; wi < 2; wi++){
      unsigned w = wR[wi];
      uint32_t t[4];
#pragma unroll
      for (int jp = 0; jp < 4; jp++){
        uint32_t u = (w & 0xFu) | ((w << 12) & 0x000F0000u) | 0x64006400u;
        __half2 h = __hsub2(*reinterpret_cast<__half2*>(&u),
                            *reinterpret_cast<__half2*>(&zc2));
        h = __hmul2(h, s2);
        t[jp] = *reinterpret_cast<uint32_t*>(&h);
        w >>= 8;
      }
      const int cch = half*2 + wi;                 // 16B chunk (8 k) index
      uint32_t off = (uint32_t)(nn*64) + (uint32_t)((cch ^ (nn&3)) << 4);
      *reinterpret_cast<uint4*>(sB + off) =
          make_uint4(t[0], t[1], t[2], t[3]);
    }
  };

  // ---- mma over one BK=32 slab (2 k16 steps) ----
  auto COMPUTE = [&](int stage){
    const uint32_t aB = sbase + (uint32_t)stage*16384u;
    const uint32_t bB = aB + 8192u;
#pragma unroll
    for (int ks = 0; ks < 2; ks++){
      uint32_t af[4][4], bf[2][4];
#pragma unroll
      for (int mt = 0; mt < 4; mt++)
        LDSM4(af[mt][0],af[mt][1],af[mt][2],af[mt][3], aB + rowA[mt] + kOff[ks]);
#pragma unroll
      for (int j = 0; j < 2; j++)
        LDSM4(bf[j][0],bf[j][1],bf[j][2],bf[j][3], bB + rowB[j] + kOff[ks]);
#pragma unroll
      for (int mt = 0; mt < 4; mt++)
#pragma unroll
        for (int nt = 0; nt < 4; nt++)
          MMA16(c[mt][nt], af[mt][0],af[mt][1],af[mt][2],af[mt][3],
                bf[nt>>1][nt&1], bf[nt>>1][(nt&1)+2]);
    }
  };

  // ---- pipelined main loop (double-buffered smem) ----
  LOAD(0);
  STORE(0);
  __syncthreads();
  for (int kt = 0; kt < NK; kt++){
    if (kt + 1 < NK) LOAD(kt + 1);
    COMPUTE(kt & 1);
    if (kt + 1 < NK) STORE((kt + 1) & 1);
    __syncthreads();
  }

  // ---- epilogue: fp32 accumulators -> C ----
  const int g  = lane >> 2, t4 = lane & 3;
  const size_t rbase = (size_t)(bm*128 + wm*64);
  const int    cbase = bn*128 + wn*32 + 2*t4;
#pragma unroll
  for (int mt = 0; mt < 4; mt++){
#pragma unroll
    for (int nt = 0; nt < 4; nt++){
      size_t o0 = (rbase + mt*16 + g) * (size_t)N + cbase + nt*8;
      *reinterpret_cast<float2*>(C + o0) =
          make_float2(c[mt][nt][0], c[mt][nt][1]);
      *reinterpret_cast<float2*>(C + o0 + (size_t)8*N) =
          make_float2(c[mt][nt][2], c[mt][nt][3]);
    }
  }
}

extern "C" void kernel_launch(void* const* d_in, const int* in_sizes, int n_in,
                              void* d_out, int out_size)
{
  const float* x  = (const float*)d_in[0];
  const int*   qw = (const int*)  d_in[1];
  const float* sc = (const float*)d_in[2];
  const int*   qz = (const int*)  d_in[3];
  // d_in[4] = g_idx (standard consecutive grouping; used only for sizes)

  const int K = in_sizes[4];
  const int M = in_sizes[0] / K;
  const int G = K / 128;
  const int N = in_sizes[2] / G;

  const int shmem = 2 * 16384;     // 32 KB: 2 stages x (A 8KB + B 8KB)
  dim3 grid(N / 128, M / 128);
  gptq_gemm_f16<<<grid, 256, shmem>>>(x, qw, sc, qz, (float*)d_out, M, N, K);
}

// round 6
// speedup vs baseline: 1.6711x; 1.2392x over previous
#include <cuda_runtime.h>
#include <cuda_fp16.h>
#include <cstdint>

// ---------------------------------------------------------------------------
// GPTQ 4-bit dequant GEMM, fp16 tensor cores (mma.sync m16n8k16), fp32 accum.
// C[M,N] = A[M,K] @ dequant(QW)   with group-128 scales/zeros along K.
// Block tile 128x256x32, 8 warps (2x4), warp tile 64x64.
// Smem rows 64B (32 fp16), 16B chunks, conflict-free hash h(r)=(r+(r>>2))&3.
// ---------------------------------------------------------------------------

#define LDSM4(R0,R1,R2,R3,addr) \
  asm volatile("ldmatrix.sync.aligned.m8n8.x4.shared.b16 {%0,%1,%2,%3}, [%4];" \
    : "=r"(R0),"=r"(R1),"=r"(R2),"=r"(R3) : "r"(addr))

#define MMA16(Cr,A0,A1,A2,A3,B0,B1) \
  asm volatile("mma.sync.aligned.m16n8k16.row.col.f32.f16.f16.f32 " \
    "{%0,%1,%2,%3},{%4,%5,%6,%7},{%8,%9},{%0,%1,%2,%3};" \
    : "+f"(Cr[0]),"+f"(Cr[1]),"+f"(Cr[2]),"+f"(Cr[3]) \
    : "r"(A0),"r"(A1),"r"(A2),"r"(A3),"r"(B0),"r"(B1))

__device__ __forceinline__ uint32_t f16x2(float lo, float hi){
  uint32_t r; asm("cvt.rn.f16x2.f32 %0, %2, %1;" : "=r"(r) : "f"(lo), "f"(hi)); return r;
}

__global__ void __launch_bounds__(256, 1)
gptq_gemm_f16w(const float* __restrict__ A, const int* __restrict__ QW,
               const float* __restrict__ SC, const int* __restrict__ QZ,
               float* __restrict__ C, int M, int N, int K)
{
  // smem: 2 stages x (A: 128 rows x 64B = 8KB, B: 256 rows x 64B = 16KB)
  extern __shared__ char smem[];
  const int STAGE = 24576;

  const int tid  = threadIdx.x;
  const int lane = tid & 31, warp = tid >> 5;
  const int wm   = warp >> 2, wn = warp & 3;       // 2 (M) x 4 (N) warp grid
  const int bm   = blockIdx.y, bn = blockIdx.x;

  // ---- ldmatrix per-thread addresses (conflict-free hash) ----
  const uint32_t sbase = (uint32_t)__cvta_generic_to_shared(smem);
  // A rows: r = (mt*16 base) + (lane&15); h depends only on lane
  const uint32_t hA = (uint32_t)(((lane & 3) + ((lane >> 2) & 3)) & 3);
  // B rows: r = base8 + (lane&7), base8 includes ((lane>>3)&1)*8
  const uint32_t hB = (uint32_t)(((lane & 3) + ((lane >> 2) & 1) + ((lane >> 3) & 1) * 2) & 3);

  uint32_t rowA[4], rowB[4], kOffA[2], kOffB[2];
#pragma unroll
  for (int mt = 0; mt < 4; mt++)
    rowA[mt] = (uint32_t)((wm*64 + mt*16 + (lane & 15)) * 64);
#pragma unroll
  for (int j = 0; j < 4; j++)
    rowB[j]  = (uint32_t)((wn*64 + j*16 + ((lane>>3)&1)*8 + (lane&7)) * 64);
#pragma unroll
  for (int ks = 0; ks < 2; ks++){
    kOffA[ks] = (uint32_t)((((uint32_t)(2*ks) + (uint32_t)(lane>>4)) ^ hA) << 4);
    kOffB[ks] = (uint32_t)((((uint32_t)(2*ks) + (uint32_t)(lane>>4)) ^ hB) << 4);
  }

  // ---- global load coordinates ----
  const int arow = tid >> 2;          // A rows 0..63 (+64 second pass)
  const int aq   = tid & 3;           // 16B chunk (8 fp32) within 32-col row
  const uint32_t hAst = (uint32_t)((((tid>>2) & 3) + ((tid>>4) & 3)) & 3); // h(arow), p*64 invariant
  const int nn   = tid;               // B n-row 0..255
  const uint32_t hBst = (uint32_t)(((nn & 3) + ((nn >> 2) & 3)) & 3);      // h(nn)
  const int ngl  = bn*256 + nn;
  const int zsh  = (ngl & 7) * 4;
  const int N8   = N >> 3;

  const float* Abase = A + (size_t)(bm*128 + arow)*K + aq*8;

  float4   aR[2][2];
  unsigned wR[4];
  uint32_t zc2 = 0;
  __half2  s2  = __half2half2(__float2half(0.f));

  float c[4][8][4];
#pragma unroll
  for (int i=0;i<4;i++)
#pragma unroll
    for (int j=0;j<8;j++)
#pragma unroll
      for (int q=0;q<4;q++) c[i][j][q]=0.f;

  const int NK = K >> 5;  // BK = 32

  auto LOAD = [&](int kt){
#pragma unroll
    for (int p = 0; p < 2; p++){
      aR[p][0] = *reinterpret_cast<const float4*>(Abase + (size_t)p*64*K + kt*32);
      aR[p][1] = *reinterpret_cast<const float4*>(Abase + (size_t)p*64*K + kt*32 + 4);
    }
    const int wrow = kt*4;
#pragma unroll
    for (int wi = 0; wi < 4; wi++)
      wR[wi] = (unsigned)QW[(size_t)(wrow+wi)*N + ngl];
    const int g = kt >> 2;                           // GROUP=128 = 4 BK tiles
    const int zq = (QZ[(size_t)g*N8 + (ngl>>3)] >> zsh) & 15;
    const uint32_t zb = 0x6400u + 1u + (uint32_t)zq; // fp16 bits of 1025+z (exact)
    zc2 = zb | (zb << 16);
    s2  = __half2half2(__float2half(SC[(size_t)g*N + ngl]));
  };

  auto STORE = [&](int stage){
    char* sA = smem + stage*STAGE;
    char* sB = sA + 8192;
    // A: fp32 -> fp16, 16B per row-chunk, hashed chunk position
#pragma unroll
    for (int p = 0; p < 2; p++){
      const int r = arow + p*64;
      uint32_t off = (uint32_t)(r*64) + ((((uint32_t)aq) ^ hAst) << 4);
      uint4 v;
      v.x = f16x2(aR[p][0].x, aR[p][0].y);
      v.y = f16x2(aR[p][0].z, aR[p][0].w);
      v.z = f16x2(aR[p][1].x, aR[p][1].y);
      v.w = f16x2(aR[p][1].z, aR[p][1].w);
      *reinterpret_cast<uint4*>(sA + off) = v;
    }
    // B: packed half2 dequant; word wi holds k = wi*8 .. wi*8+7 (one 16B chunk)
#pragma unroll
    for (int wi = 0; wi < 4; wi++){
      unsigned w = wR[wi];
      uint32_t t[4];
#pragma unroll
      for (int jp = 0; jp < 4; jp++){
        uint32_t u = (w & 0xFu) | ((w << 12) & 0x000F0000u) | 0x64006400u;
        __half2 h = __hsub2(*reinterpret_cast<__half2*>(&u),
                            *reinterpret_cast<__half2*>(&zc2));
        h = __hmul2(h, s2);
        t[jp] = *reinterpret_cast<uint32_t*>(&h);
        w >>= 8;
      }
      uint32_t off = (uint32_t)(nn*64) + ((((uint32_t)wi) ^ hBst) << 4);
      *reinterpret_cast<uint4*>(sB + off) = make_uint4(t[0], t[1], t[2], t[3]);
    }
  };

  auto COMPUTE = [&](int stage){
    const uint32_t aB = sbase + (uint32_t)(stage*STAGE);
    const uint32_t bB = aB + 8192u;
#pragma unroll
    for (int ks = 0; ks < 2; ks++){
      uint32_t af[4][4], bf[4][4];
#pragma unroll
      for (int mt = 0; mt < 4; mt++)
        LDSM4(af[mt][0],af[mt][1],af[mt][2],af[mt][3], aB + rowA[mt] + kOffA[ks]);
#pragma unroll
      for (int j = 0; j < 4; j++)
        LDSM4(bf[j][0],bf[j][1],bf[j][2],bf[j][3], bB + rowB[j] + kOffB[ks]);
#pragma unroll
      for (int mt = 0; mt < 4; mt++)
#pragma unroll
        for (int nt = 0; nt < 8; nt++)
          MMA16(c[mt][nt], af[mt][0],af[mt][1],af[mt][2],af[mt][3],
                bf[nt>>1][nt&1], bf[nt>>1][(nt&1)+2]);
    }
  };

  // ---- pipelined main loop (double-buffered smem) ----
  LOAD(0);
  STORE(0);
  __syncthreads();
  for (int kt = 0; kt < NK; kt++){
    if (kt + 1 < NK) LOAD(kt + 1);
    COMPUTE(kt & 1);
    if (kt + 1 < NK) STORE((kt + 1) & 1);
    __syncthreads();
  }

  // ---- epilogue: fp32 accumulators -> C ----
  const int g  = lane >> 2, t4 = lane & 3;
  const size_t rbase = (size_t)(bm*128 + wm*64);
  const int    cbase = bn*256 + wn*64 + 2*t4;
#pragma unroll
  for (int mt = 0; mt < 4; mt++){
#pragma unroll
    for (int nt = 0; nt < 8; nt++){
      size_t o0 = (rbase + mt*16 + g) * (size_t)N + cbase + nt*8;
      *reinterpret_cast<float2*>(C + o0) =
          make_float2(c[mt][nt][0], c[mt][nt][1]);
      *reinterpret_cast<float2*>(C + o0 + (size_t)8*N) =
          make_float2(c[mt][nt][2], c[mt][nt][3]);
    }
  }
}

extern "C" void kernel_launch(void* const* d_in, const int* in_sizes, int n_in,
                              void* d_out, int out_size)
{
  const float* x  = (const float*)d_in[0];
  const int*   qw = (const int*)  d_in[1];
  const float* sc = (const float*)d_in[2];
  const int*   qz = (const int*)  d_in[3];
  // d_in[4] = g_idx (standard consecutive grouping; used only for sizes)

  const int K = in_sizes[4];
  const int M = in_sizes[0] / K;
  const int G = K / 128;
  const int N = in_sizes[2] / G;

  const int shmem = 2 * 24576;     // 48 KB: 2 stages x (A 8KB + B 16KB)
  cudaFuncSetAttribute(gptq_gemm_f16w,
                       cudaFuncAttributeMaxDynamicSharedMemorySize, shmem);

  dim3 grid(N / 256, M / 128);
  gptq_gemm_f16w<<<grid, 256, shmem>>>(x, qw, sc, qz, (float*)d_out, M, N, K);
}

// round 12
// speedup vs baseline: 1.6861x; 1.0090x over previous
#include <cuda_runtime.h>
#include <cuda_fp16.h>
#include <cstdint>

// ---------------------------------------------------------------------------
// GPTQ 4-bit dequant GEMM, fp16 tensor cores (mma.sync m16n8k16), fp32 accum.
// Two kernels: (1) A fp32->fp16 pre-convert into __device__ scratch,
// (2) GEMM: block tile 128x256x64, 8 warps (2x4), warp tile 64x64.
// Smem rows 128B, XOR-8 16B-chunk swizzle; A via cp.async, B dequant in regs.
// ---------------------------------------------------------------------------

__device__ __align__(16) __half g_A16[4096ull * 4096ull];   // scratch (32 MB)

#define LDSM4(R0,R1,R2,R3,addr) \
  asm volatile("ldmatrix.sync.aligned.m8n8.x4.shared.b16 {%0,%1,%2,%3}, [%4];" \
    : "=r"(R0),"=r"(R1),"=r"(R2),"=r"(R3) : "r"(addr))

#define MMA16(Cr,A0,A1,A2,A3,B0,B1) \
  asm volatile("mma.sync.aligned.m16n8k16.row.col.f32.f16.f16.f32 " \
    "{%0,%1,%2,%3},{%4,%5,%6,%7},{%8,%9},{%0,%1,%2,%3};" \
    : "+f"(Cr[0]),"+f"(Cr[1]),"+f"(Cr[2]),"+f"(Cr[3]) \
    : "r"(A0),"r"(A1),"r"(A2),"r"(A3),"r"(B0),"r"(B1))

#define CPASYNC16(dst, src) \
  asm volatile("cp.async.cg.shared.global [%0], [%1], 16;" :: "r"(dst), "l"(src))
#define CPCOMMIT() asm volatile("cp.async.commit_group;" ::: "memory")
#define CPWAIT0()  asm volatile("cp.async.wait_group 0;" ::: "memory")

__device__ __forceinline__ uint32_t f16x2(float lo, float hi){
  uint32_t r; asm("cvt.rn.f16x2.f32 %0, %2, %1;" : "=r"(r) : "f"(lo), "f"(hi)); return r;
}

// ---- kernel 1: A fp32 -> fp16 ----
__global__ void __launch_bounds__(256)
conv_a_kernel(const float* __restrict__ A, int total8){
  int i = blockIdx.x * blockDim.x + threadIdx.x;
  if (i >= total8) return;
  const float4* p = reinterpret_cast<const float4*>(A);
  float4 v0 = p[2*i], v1 = p[2*i+1];
  uint4 o;
  o.x = f16x2(v0.x, v0.y); o.y = f16x2(v0.z, v0.w);
  o.z = f16x2(v1.x, v1.y); o.w = f16x2(v1.z, v1.w);
  reinterpret_cast<uint4*>(g_A16)[i] = o;
}

// ---- kernel 2: GEMM ----
__global__ void __launch_bounds__(256, 1)
gptq_f16_cp(const int* __restrict__ QW, const float* __restrict__ SC,
            const int* __restrict__ QZ, float* __restrict__ C,
            int M, int N, int K)
{
  // smem: 2 stages x (A: 128 rows x 128B = 16KB, B: 256 rows x 128B = 32KB)
  extern __shared__ char smem[];
  const int STAGE = 49152;

  const int tid  = threadIdx.x;
  const int lane = tid & 31, warp = tid >> 5;
  const int wm   = warp >> 2, wn = warp & 3;       // 2 (M) x 4 (N)
  const int bm   = blockIdx.y, bn = blockIdx.x;

  const uint32_t sbase = (uint32_t)__cvta_generic_to_shared(smem);
  uint32_t rowA[4], rowB[4], kOff[4];
#pragma unroll
  for (int mt = 0; mt < 4; mt++)
    rowA[mt] = (uint32_t)((wm*64 + mt*16 + (lane & 15)) * 128);
#pragma unroll
  for (int j = 0; j < 4; j++)
    rowB[j]  = (uint32_t)((wn*64 + j*16 + ((lane>>3)&1)*8 + (lane&7)) * 128);
#pragma unroll
  for (int ks = 0; ks < 4; ks++)
    kOff[ks] = (uint32_t)(((2*ks + (lane>>4)) ^ (lane & 7)) << 4);

  // A cp.async coords: 2 threads per row, 4 x 16B chunks each
  const int ar  = tid >> 1;
  const int ac4 = (tid & 1) * 4;
  const __half* Ag = g_A16 + (size_t)(bm*128 + ar)*K;

  // B coords: thread owns n-row nn (all 64 k of it)
  const int nn  = tid;
  const int ngl = bn*256 + nn;
  const int zsh = (ngl & 7) * 4;
  const int N8  = N >> 3;

  unsigned wR[8];
  uint32_t zc2 = 0;
  __half2  s2  = __half2half2(__float2half(0.f));

  float c[4][8][4];
#pragma unroll
  for (int i=0;i<4;i++)
#pragma unroll
    for (int j=0;j<8;j++)
#pragma unroll
      for (int q=0;q<4;q++) c[i][j][q]=0.f;

  const int NK = K >> 6;   // BK = 64

  auto CPA = [&](int kt, int stage){
    const uint32_t dbase = sbase + (uint32_t)(stage*STAGE);
    const __half* src = Ag + kt*64;
#pragma unroll
    for (int i = 0; i < 4; i++){
      const int ch = ac4 + i;
      const uint32_t off = (uint32_t)(ar*128) + (uint32_t)((ch ^ (ar&7)) << 4);
      CPASYNC16(dbase + off, src + ch*8);
    }
  };

  auto LDGB = [&](int kt){
    const int wrow = kt*8;
#pragma unroll
    for (int wi = 0; wi < 8; wi++)
      wR[wi] = (unsigned)QW[(size_t)(wrow+wi)*N + ngl];
    if ((kt & 1) == 0){                         // GROUP=128 = 2 k-tiles
      const int g  = kt >> 1;
      const int zq = (QZ[(size_t)g*N8 + (ngl>>3)] >> zsh) & 15;
      const uint32_t zb = 0x6400u + 1u + (uint32_t)zq;  // fp16 bits 1025+z
      zc2 = zb | (zb << 16);
      s2  = __half2half2(__float2half(SC[(size_t)g*N + ngl]));
    }
  };

  auto STOREB = [&](int stage){
    char* sB = smem + stage*STAGE + 16384;
#pragma unroll
    for (int wi = 0; wi < 8; wi++){
      unsigned w = wR[wi];
      uint32_t t[4];
#pragma unroll
      for (int jp = 0; jp < 4; jp++){
        uint32_t u = (w & 0xFu) | ((w << 12) & 0x000F0000u) | 0x64006400u;
        __half2 h = __hsub2(*reinterpret_cast<__half2*>(&u),
                            *reinterpret_cast<__half2*>(&zc2));
        h = __hmul2(h, s2);
        t[jp] = *reinterpret_cast<uint32_t*>(&h);
        w >>= 8;
      }
      const uint32_t off = (uint32_t)(nn*128) + (uint32_t)((wi ^ (nn&7)) << 4);
      *reinterpret_cast<uint4*>(sB + off) = make_uint4(t[0], t[1], t[2], t[3]);
    }
  };

  auto COMPUTE = [&](int stage){
    const uint32_t aB = sbase + (uint32_t)(stage*STAGE);
    const uint32_t bB = aB + 16384u;
#pragma unroll
    for (int ks = 0; ks < 4; ks++){
      uint32_t af[4][4], bf[4][4];
#pragma unroll
      for (int mt = 0; mt < 4; mt++)
        LDSM4(af[mt][0],af[mt][1],af[mt][2],af[mt][3], aB + rowA[mt] + kOff[ks]);
#pragma unroll
      for (int j = 0; j < 4; j++)
        LDSM4(bf[j][0],bf[j][1],bf[j][2],bf[j][3], bB + rowB[j] + kOff[ks]);
#pragma unroll
      for (int mt = 0; mt < 4; mt++)
#pragma unroll
        for (int nt = 0; nt < 8; nt++)
          MMA16(c[mt][nt], af[mt][0],af[mt][1],af[mt][2],af[mt][3],
                bf[nt>>1][nt&1], bf[nt>>1][(nt&1)+2]);
    }
  };

  // ---- prologue ----
  CPA(0, 0); CPCOMMIT();
  LDGB(0);
  STOREB(0);
  CPWAIT0();
  __syncthreads();

  // ---- main loop ----
  for (int kt = 0; kt < NK; kt++){
    const int s = kt & 1;
    if (kt + 1 < NK){
      CPA(kt + 1, s ^ 1); CPCOMMIT();
      LDGB(kt + 1);
    }
    COMPUTE(s);
    if (kt + 1 < NK){
      STOREB(s ^ 1);
      CPWAIT0();
    }
    __syncthreads();
  }

  // ---- epilogue ----
  const int g  = lane >> 2, t4 = lane & 3;
  const size_t rbase = (size_t)(bm*128 + wm*64);
  const int    cbase = bn*256 + wn*64 + 2*t4;
#pragma unroll
  for (int mt = 0; mt < 4; mt++){
#pragma unroll
    for (int nt = 0; nt < 8; nt++){
      size_t o0 = (rbase + mt*16 + g) * (size_t)N + cbase + nt*8;
      *reinterpret_cast<float2*>(C + o0) =
          make_float2(c[mt][nt][0], c[mt][nt][1]);
      *reinterpret_cast<float2*>(C + o0 + (size_t)8*N) =
          make_float2(c[mt][nt][2], c[mt][nt][3]);
    }
  }
}

extern "C" void kernel_launch(void* const* d_in, const int* in_sizes, int n_in,
                              void* d_out, int out_size)
{
  const float* x  = (const float*)d_in[0];
  const int*   qw = (const int*)  d_in[1];
  const float* sc = (const float*)d_in[2];
  const int*   qz = (const int*)  d_in[3];
  // d_in[4] = g_idx (standard consecutive grouping; used only for sizes)

  const int K = in_sizes[4];
  const int M = in_sizes[0] / K;
  const int G = K / 128;
  const int N = in_sizes[2] / G;

  const int total8 = (M * K) / 8;
  conv_a_kernel<<<(total8 + 255) / 256, 256>>>(x, total8);

  const int shmem = 2 * 49152;    // 96 KB
  cudaFuncSetAttribute(gptq_f16_cp,
                       cudaFuncAttributeMaxDynamicSharedMemorySize, shmem);
  dim3 grid(N / 256, M / 128);
  gptq_f16_cp<<<grid, 256, shmem>>>(qw, sc, qz, (float*)d_out, M, N, K);
}